// round 5
// baseline (speedup 1.0000x reference)
#include <cuda_runtime.h>
#include <cuda_bf16.h>
#include <cstdint>

#define K1    1521
#define K2    4992
#define NC1   24            // 1536/64
#define NC2   78            // 4992/64
#define NCT   (NC1 + NC2)   // 102
#define F0n   39
#define Dn    16
#define HOUT  256

// ---- SMEM layout (bytes) ----
#define BUF_SZ    65536
#define XS_OFF    131072                  // float xs[128][40]
#define H1S_OFF   151552                  // float h1s[128][132]
#define SMEM_TOTAL 219136

// Pre-split weights, [chunk][h(128)][kl(64)] bf16, zero-padded past K1.
__device__ __nv_bfloat16 g_Whi[NCT * 8192];
__device__ __nv_bfloat16 g_Wlo[NCT * 8192];

__device__ __forceinline__ uint32_t smem_u32(const void* p) {
    uint32_t a;
    asm("{ .reg .u64 t; cvta.to.shared.u64 t, %1; cvt.u32.u64 %0, t; }" : "=r"(a) : "l"(p));
    return a;
}

#define CP16(dst, src) \
    asm volatile("cp.async.cg.shared.global [%0], [%1], 16;" :: "r"(dst), "l"(src))
#define CP_COMMIT() asm volatile("cp.async.commit_group;" ::: "memory")
#define CP_WAIT0()  asm volatile("cp.async.wait_group 0;" ::: "memory")

#define LDSM_X4(r0, r1, r2, r3, addr) \
    asm volatile("ldmatrix.sync.aligned.m8n8.x4.shared.b16 {%0,%1,%2,%3}, [%4];" \
                 : "=r"(r0), "=r"(r1), "=r"(r2), "=r"(r3) : "r"(addr))

#define MMA16816(d, a, b0_, b1_) \
    asm volatile("mma.sync.aligned.m16n8k16.row.col.f32.bf16.bf16.f32 " \
                 "{%0,%1,%2,%3}, {%4,%5,%6,%7}, {%8,%9}, {%0,%1,%2,%3};" \
                 : "+f"((d)[0]), "+f"((d)[1]), "+f"((d)[2]), "+f"((d)[3]) \
                 : "r"((a)[0]), "r"((a)[1]), "r"((a)[2]), "r"((a)[3]), \
                   "r"(b0_), "r"(b1_))

// ---------------- weight prep: split hi/lo bf16 ----------------
__global__ void prep_w(const float* __restrict__ W0, const float* __restrict__ W1) {
    int idx = blockIdx.x * 256 + threadIdx.x;
    if (idx >= NCT * 8192) return;
    int chunk = idx >> 13;
    int h = (idx >> 6) & 127;
    int kl = idx & 63;
    float w = 0.f;
    if (chunk < NC1) {
        int k = chunk * 64 + kl;
        if (k < K1) w = W0[h * K1 + k];
    } else {
        int k = (chunk - NC1) * 64 + kl;
        w = W1[h * K2 + k];
    }
    __nv_bfloat16 hi = __float2bfloat16(w);
    __nv_bfloat16 lo = __float2bfloat16(w - __bfloat162float(hi));
    g_Whi[idx] = hi;
    g_Wlo[idx] = lo;
}

// ---------------- device helpers ----------------
__device__ __forceinline__ void stage_w(uint32_t sb, int bb, int chunk, int tid) {
    const uint32_t wbase = sb + bb * BUF_SZ + 32768;
    #pragma unroll
    for (int t = 0; t < 4; t++) {
        int i = tid + t * 512;            // 0..2047
        int tile = i >> 10;               // 0=hi, 1=lo
        int h = (i >> 3) & 127;
        int seg = i & 7;
        const __nv_bfloat16* src =
            (tile ? g_Wlo : g_Whi) + chunk * 8192 + h * 64 + seg * 8;
        uint32_t dst = wbase + tile * 16384 + h * 128 + ((seg * 16) ^ ((h & 7) << 4));
        CP16(dst, src);
    }
}

// z-build state precomputed per chunk
struct ZCtx {
    const float* a_col;    // xs + f
    const float* b_col;    // xs/h1s + q
    int bstride;
    char* zhi;             // dest tile base
    uint32_t cb;           // kl*2
    bool valid;
};

__device__ __forceinline__ ZCtx z_prepare(char* smem, int bb, int layer, int c, int tid) {
    ZCtx ctx;
    const float* xs  = (const float*)(smem + XS_OFF);
    const float* h1s = (const float*)(smem + H1S_OFF);
    const int kl = tid & 63;
    const int k = c * 64 + kl;
    int f = 0, q = 0;
    ctx.valid = true;
    if (layer == 0) {
        if (k < K1) { f = k / 39; q = k - f * 39; } else ctx.valid = false;
    } else { f = k >> 7; q = k & 127; }
    ctx.a_col = xs + f;
    ctx.b_col = layer ? (h1s + q) : (xs + q);
    ctx.bstride = layer ? 132 : 40;
    ctx.zhi = smem + bb * BUF_SZ;
    ctx.cb = (uint32_t)(kl * 2);
    return ctx;
}

// build 4 rows of the z tile (rows n0+r0 .. n0+r0+3), n0 = (tid>>6)*16
__device__ __forceinline__ void z_slice(const ZCtx& ctx, int tid, int r0) {
    const int n0 = (tid >> 6) * 16 + r0;
    #pragma unroll
    for (int nn = 0; nn < 4; nn++) {
        const int n = n0 + nn;
        float zv = 0.f;
        if (ctx.valid) zv = ctx.a_col[n * 40] * ctx.b_col[n * ctx.bstride];
        __nv_bfloat16 hi = __float2bfloat16(zv);
        __nv_bfloat16 lo = __float2bfloat16(zv - __bfloat162float(hi));
        uint32_t off = (uint32_t)(n * 128) + (ctx.cb ^ ((uint32_t)(n & 7) << 4));
        *(__nv_bfloat16*)(ctx.zhi + off) = hi;
        *(__nv_bfloat16*)(ctx.zhi + 16384 + off) = lo;
    }
}

// MMA over chunk bb, with next-chunk z-build slices interleaved into the ks loop
__device__ __forceinline__ void mma_chunk(uint32_t sb, int bb, float acc[2][4][4],
                                          int m0, int h0, int lane,
                                          const ZCtx& zctx, bool do_z, int tid) {
    const uint32_t zb = sb + bb * BUF_SZ;
    const uint32_t wb = zb + 32768;
    #pragma unroll
    for (int ks = 0; ks < 4; ks++) {
        const int kb = ks * 16;
        uint32_t a_hi[2][4], a_lo[2][4];
        const uint32_t acolb = (uint32_t)((kb + (lane >> 4) * 8) * 2);
        #pragma unroll
        for (int mt = 0; mt < 2; mt++) {
            const int n = m0 + mt * 16 + (lane & 15);
            const uint32_t ad = zb + n * 128 + (acolb ^ ((uint32_t)(n & 7) << 4));
            LDSM_X4(a_hi[mt][0], a_hi[mt][1], a_hi[mt][2], a_hi[mt][3], ad);
            LDSM_X4(a_lo[mt][0], a_lo[mt][1], a_lo[mt][2], a_lo[mt][3], ad + 16384);
        }
        uint32_t b_hi[8], b_lo[8];
        const uint32_t bcolb = (uint32_t)((kb + ((lane >> 3) & 1) * 8) * 2);
        #pragma unroll
        for (int pr = 0; pr < 2; pr++) {
            const int h = h0 + pr * 16 + (lane >> 4) * 8 + (lane & 7);
            const uint32_t bd = wb + h * 128 + (bcolb ^ ((uint32_t)(h & 7) << 4));
            LDSM_X4(b_hi[pr * 4 + 0], b_hi[pr * 4 + 1], b_hi[pr * 4 + 2], b_hi[pr * 4 + 3], bd);
            LDSM_X4(b_lo[pr * 4 + 0], b_lo[pr * 4 + 1], b_lo[pr * 4 + 2], b_lo[pr * 4 + 3], bd + 16384);
        }
        // next-chunk z-build slice: fma/alu/LSU work issued under the tensor stream
        if (do_z) z_slice(zctx, tid, ks * 4);
        #pragma unroll
        for (int mt = 0; mt < 2; mt++)
            #pragma unroll
            for (int ht = 0; ht < 4; ht++) {
                MMA16816(acc[mt][ht], a_hi[mt], b_hi[ht * 2], b_hi[ht * 2 + 1]);
                MMA16816(acc[mt][ht], a_hi[mt], b_lo[ht * 2], b_lo[ht * 2 + 1]);
                MMA16816(acc[mt][ht], a_lo[mt], b_hi[ht * 2], b_hi[ht * 2 + 1]);
            }
    }
}

// ---------------- main kernel ----------------
__global__ __launch_bounds__(512, 1)
void cin_main(const float* __restrict__ x, float* __restrict__ out) {
    extern __shared__ __align__(1024) char smem[];
    const uint32_t sb = smem_u32(smem);
    float* xs  = (float*)(smem + XS_OFF);
    float* h1s = (float*)(smem + H1S_OFF);

    const int tid = threadIdx.x;
    const int lane = tid & 31;
    const int warp = tid >> 5;
    const int m0 = (warp & 3) * 32;       // n-rows (4 groups of 32)
    const int h0 = (warp >> 2) * 32;      // h-cols (4 groups of 32)
    const int b0 = blockIdx.x * 8;

    // load x tile transposed: xs[n][f], n = (b_local<<4)|d
    for (int i = tid; i < F0n * 128; i += 512) {
        int f = i >> 7, c = i & 127;
        int b = b0 + (c >> 4), d = c & 15;
        xs[c * 40 + f] = x[(b * F0n + f) * Dn + d];
    }
    __syncthreads();

    float acc[2][4][4];

    #pragma unroll 1
    for (int layer = 0; layer < 2; layer++) {
        const int nc = layer ? NC2 : NC1;
        const int cbase = layer ? NC1 : 0;

        #pragma unroll
        for (int mt = 0; mt < 2; mt++)
            #pragma unroll
            for (int ht = 0; ht < 4; ht++)
                #pragma unroll
                for (int j = 0; j < 4; j++) acc[mt][ht][j] = 0.f;

        // prologue: stage + build chunk 0
        stage_w(sb, 0, cbase, tid);
        CP_COMMIT();
        {
            ZCtx z0 = z_prepare(smem, 0, layer, 0, tid);
            #pragma unroll
            for (int r = 0; r < 4; r++) z_slice(z0, tid, r * 4);
        }
        CP_WAIT0();
        __syncthreads();

        #pragma unroll 1
        for (int c = 0; c < nc; c++) {
            const int bb = c & 1;
            const int nb = bb ^ 1;
            const bool more = (c + 1 < nc);
            if (more) { stage_w(sb, nb, cbase + c + 1, tid); CP_COMMIT(); }
            ZCtx zctx = z_prepare(smem, nb, layer, c + 1, tid);
            mma_chunk(sb, bb, acc, m0, h0, lane, zctx, more, tid);
            CP_WAIT0();
            __syncthreads();
        }

        // store acc -> h1s[n][h] (fp32)
        {
            const int r = lane >> 2;
            const int cc = (lane & 3) * 2;
            #pragma unroll
            for (int mt = 0; mt < 2; mt++)
                #pragma unroll
                for (int ht = 0; ht < 4; ht++) {
                    const int n = m0 + mt * 16 + r;
                    const int h = h0 + ht * 8 + cc;
                    *(float2*)&h1s[n * 132 + h] =
                        make_float2(acc[mt][ht][0], acc[mt][ht][1]);
                    *(float2*)&h1s[(n + 8) * 132 + h] =
                        make_float2(acc[mt][ht][2], acc[mt][ht][3]);
                }
        }
        __syncthreads();

        // out[b][h] = sum_d h1s[(bl*16+d)][h]
        const int obase = layer ? 128 : 0;
        #pragma unroll
        for (int rr = 0; rr < 2; rr++) {
            const int idx = rr * 512 + tid;
            const int bl = idx >> 7, h = idx & 127;
            float s = 0.f;
            #pragma unroll
            for (int d = 0; d < 16; d++) s += h1s[(bl * 16 + d) * 132 + h];
            out[(b0 + bl) * HOUT + obase + h] = s;
        }
        __syncthreads();
    }
}

extern "C" void kernel_launch(void* const* d_in, const int* in_sizes, int n_in,
                              void* d_out, int out_size) {
    const float* xin = (const float*)d_in[0];
    const float* W0  = (const float*)d_in[1];
    const float* W1  = (const float*)d_in[2];
    float* out = (float*)d_out;

    prep_w<<<(NCT * 8192 + 255) / 256, 256>>>(W0, W1);

    cudaFuncSetAttribute(cin_main, cudaFuncAttributeMaxDynamicSharedMemorySize, SMEM_TOTAL);
    cin_main<<<256, 512, SMEM_TOTAL>>>(xin, out);
}

// round 6
// speedup vs baseline: 1.1177x; 1.1177x over previous
#include <cuda_runtime.h>
#include <cuda_bf16.h>
#include <cstdint>

#define K1    1521
#define K2    4992
#define NC1   24            // 1536/64
#define NC2   78            // 4992/64
#define NCT   (NC1 + NC2)   // 102
#define F0n   39
#define Dn    16
#define HOUT  256

#define BUF_SZ    65536
#define XS_OFF    131072                  // float xs[128][40]
#define H1S_OFF   151552                  // float h1s[128][132]
#define SMEM_TOTAL 219136

__device__ __nv_bfloat16 g_Whi[NCT * 8192];
__device__ __nv_bfloat16 g_Wlo[NCT * 8192];

__device__ __forceinline__ uint32_t smem_u32(const void* p) {
    uint32_t a;
    asm("{ .reg .u64 t; cvta.to.shared.u64 t, %1; cvt.u32.u64 %0, t; }" : "=r"(a) : "l"(p));
    return a;
}

#define CP16(dst, src) \
    asm volatile("cp.async.cg.shared.global [%0], [%1], 16;" :: "r"(dst), "l"(src))
#define CP_COMMIT() asm volatile("cp.async.commit_group;" ::: "memory")
#define CP_WAIT0()  asm volatile("cp.async.wait_group 0;" ::: "memory")

#define LDSM_X4(r0, r1, r2, r3, addr) \
    asm volatile("ldmatrix.sync.aligned.m8n8.x4.shared.b16 {%0,%1,%2,%3}, [%4];" \
                 : "=r"(r0), "=r"(r1), "=r"(r2), "=r"(r3) : "r"(addr))

#define MMA16816(d, a, b0_, b1_) \
    asm volatile("mma.sync.aligned.m16n8k16.row.col.f32.bf16.bf16.f32 " \
                 "{%0,%1,%2,%3}, {%4,%5,%6,%7}, {%8,%9}, {%0,%1,%2,%3};" \
                 : "+f"((d)[0]), "+f"((d)[1]), "+f"((d)[2]), "+f"((d)[3]) \
                 : "r"((a)[0]), "r"((a)[1]), "r"((a)[2]), "r"((a)[3]), \
                   "r"(b0_), "r"(b1_))

// ---------------- weight prep: split hi/lo bf16 ----------------
__global__ void prep_w(const float* __restrict__ W0, const float* __restrict__ W1) {
    int idx = blockIdx.x * 256 + threadIdx.x;
    if (idx >= NCT * 8192) return;
    int chunk = idx >> 13;
    int h = (idx >> 6) & 127;
    int kl = idx & 63;
    float w = 0.f;
    if (chunk < NC1) {
        int k = chunk * 64 + kl;
        if (k < K1) w = W0[h * K1 + k];
    } else {
        int k = (chunk - NC1) * 64 + kl;
        w = W1[h * K2 + k];
    }
    __nv_bfloat16 hi = __float2bfloat16(w);
    __nv_bfloat16 lo = __float2bfloat16(w - __bfloat162float(hi));
    g_Whi[idx] = hi;
    g_Wlo[idx] = lo;
}

// ---------------- device helpers ----------------
__device__ __forceinline__ void stage_w(uint32_t sb, int bb, int chunk, int tid) {
    const uint32_t wbase = sb + bb * BUF_SZ + 32768;
    #pragma unroll
    for (int t = 0; t < 4; t++) {
        int i = tid + t * 512;            // 0..2047
        int tile = i >> 10;               // 0=hi, 1=lo
        int h = (i >> 3) & 127;
        int seg = i & 7;
        const __nv_bfloat16* src =
            (tile ? g_Wlo : g_Whi) + chunk * 8192 + h * 64 + seg * 8;
        uint32_t dst = wbase + tile * 16384 + h * 128 + ((seg * 16) ^ ((h & 7) << 4));
        CP16(dst, src);
    }
}

// z-build: thread owns kl-pair (2 adjacent kl) x 8 n-rows -> STS.32
__device__ __forceinline__ void build_z(char* smem, int bb, int layer, int c, int tid) {
    const float* xs  = (const float*)(smem + XS_OFF);
    const float* h1s = (const float*)(smem + H1S_OFF);
    char* zhi = smem + bb * BUF_SZ;
    const int klp = (tid & 31) * 2;         // kl pair base
    const int n0  = (tid >> 5) * 8;         // 16 groups of 8 rows
    int f0 = 0, q0 = 0, f1 = 0, q1 = 0;
    bool v0 = true, v1 = true;
    {
        const int k0 = c * 64 + klp, k1_ = k0 + 1;
        if (layer == 0) {
            if (k0 < K1) { f0 = k0 / 39; q0 = k0 - f0 * 39; } else v0 = false;
            if (k1_ < K1) { f1 = k1_ / 39; q1 = k1_ - f1 * 39; } else v1 = false;
        } else {
            f0 = k0 >> 7; q0 = k0 & 127;
            f1 = k1_ >> 7; q1 = k1_ & 127;
        }
    }
    const int bstride = layer ? 132 : 40;
    const float* bbase = layer ? h1s : xs;
    const uint32_t cb = (uint32_t)(klp * 2);
    #pragma unroll
    for (int nn = 0; nn < 8; nn++) {
        const int n = n0 + nn;
        float z0 = v0 ? xs[n * 40 + f0] * bbase[n * bstride + q0] : 0.f;
        float z1 = v1 ? xs[n * 40 + f1] * bbase[n * bstride + q1] : 0.f;
        __nv_bfloat16 h0_ = __float2bfloat16(z0);
        __nv_bfloat16 h1_ = __float2bfloat16(z1);
        __nv_bfloat16 l0_ = __float2bfloat16(z0 - __bfloat162float(h0_));
        __nv_bfloat16 l1_ = __float2bfloat16(z1 - __bfloat162float(h1_));
        uint32_t off = (uint32_t)(n * 128) + (cb ^ ((uint32_t)(n & 7) << 4));
        *(__nv_bfloat162*)(zhi + off) = __nv_bfloat162(h0_, h1_);
        *(__nv_bfloat162*)(zhi + 16384 + off) = __nv_bfloat162(l0_, l1_);
    }
}

// MMA over chunk bb; ks order rotated per warp; hi-first issue; product-major MMA order
__device__ __forceinline__ void mma_chunk(uint32_t sb, int bb, float acc[2][4][4],
                                          int m0, int h0, int lane, int ks0) {
    const uint32_t zb = sb + bb * BUF_SZ;
    const uint32_t wb = zb + 32768;
    #pragma unroll
    for (int kk = 0; kk < 4; kk++) {
        const int ks = (kk + ks0) & 3;
        const int kb = ks * 16;
        uint32_t a_hi[2][4], a_lo[2][4];
        uint32_t b_hi[8], b_lo[8];
        const uint32_t acolb = (uint32_t)((kb + (lane >> 4) * 8) * 2);
        const uint32_t bcolb = (uint32_t)((kb + ((lane >> 3) & 1) * 8) * 2);
        uint32_t ad[2], bd[2];
        #pragma unroll
        for (int mt = 0; mt < 2; mt++) {
            const int n = m0 + mt * 16 + (lane & 15);
            ad[mt] = zb + n * 128 + (acolb ^ ((uint32_t)(n & 7) << 4));
        }
        #pragma unroll
        for (int pr = 0; pr < 2; pr++) {
            const int h = h0 + pr * 16 + (lane >> 4) * 8 + (lane & 7);
            bd[pr] = wb + h * 128 + (bcolb ^ ((uint32_t)(h & 7) << 4));
        }
        // hi fragments first
        #pragma unroll
        for (int mt = 0; mt < 2; mt++)
            LDSM_X4(a_hi[mt][0], a_hi[mt][1], a_hi[mt][2], a_hi[mt][3], ad[mt]);
        #pragma unroll
        for (int pr = 0; pr < 2; pr++)
            LDSM_X4(b_hi[pr * 4 + 0], b_hi[pr * 4 + 1], b_hi[pr * 4 + 2], b_hi[pr * 4 + 3], bd[pr]);
        // lo fragments issued before hi MMAs consume hi regs (loads fly under MMA)
        #pragma unroll
        for (int mt = 0; mt < 2; mt++)
            LDSM_X4(a_lo[mt][0], a_lo[mt][1], a_lo[mt][2], a_lo[mt][3], ad[mt] + 16384);
        #pragma unroll
        for (int pr = 0; pr < 2; pr++)
            LDSM_X4(b_lo[pr * 4 + 0], b_lo[pr * 4 + 1], b_lo[pr * 4 + 2], b_lo[pr * 4 + 3], bd[pr] + 16384);
        // product-major: 8 independent accs per product block
        #pragma unroll
        for (int mt = 0; mt < 2; mt++)
            #pragma unroll
            for (int ht = 0; ht < 4; ht++)
                MMA16816(acc[mt][ht], a_hi[mt], b_hi[ht * 2], b_hi[ht * 2 + 1]);
        #pragma unroll
        for (int mt = 0; mt < 2; mt++)
            #pragma unroll
            for (int ht = 0; ht < 4; ht++)
                MMA16816(acc[mt][ht], a_hi[mt], b_lo[ht * 2], b_lo[ht * 2 + 1]);
        #pragma unroll
        for (int mt = 0; mt < 2; mt++)
            #pragma unroll
            for (int ht = 0; ht < 4; ht++)
                MMA16816(acc[mt][ht], a_lo[mt], b_hi[ht * 2], b_hi[ht * 2 + 1]);
    }
}

// ---------------- main kernel ----------------
__global__ __launch_bounds__(512, 1)
void cin_main(const float* __restrict__ x, float* __restrict__ out) {
    extern __shared__ __align__(1024) char smem[];
    const uint32_t sb = smem_u32(smem);
    float* xs  = (float*)(smem + XS_OFF);
    float* h1s = (float*)(smem + H1S_OFF);

    const int tid = threadIdx.x;
    const int lane = tid & 31;
    const int warp = tid >> 5;
    const int m0 = (warp & 3) * 32;
    const int h0 = (warp >> 2) * 32;
    const int ks0 = warp & 3;             // stagger k-step start per warp
    const int b0 = blockIdx.x * 8;

    for (int i = tid; i < F0n * 128; i += 512) {
        int f = i >> 7, c = i & 127;
        int b = b0 + (c >> 4), d = c & 15;
        xs[c * 40 + f] = x[(b * F0n + f) * Dn + d];
    }
    __syncthreads();

    float acc[2][4][4];

    #pragma unroll 1
    for (int layer = 0; layer < 2; layer++) {
        const int nc = layer ? NC2 : NC1;
        const int cbase = layer ? NC1 : 0;

        #pragma unroll
        for (int mt = 0; mt < 2; mt++)
            #pragma unroll
            for (int ht = 0; ht < 4; ht++)
                #pragma unroll
                for (int j = 0; j < 4; j++) acc[mt][ht][j] = 0.f;

        stage_w(sb, 0, cbase, tid);
        CP_COMMIT();
        build_z(smem, 0, layer, 0, tid);
        CP_WAIT0();
        __syncthreads();

        #pragma unroll 1
        for (int c = 0; c < nc; c++) {
            const int bb = c & 1;
            const int nb = bb ^ 1;
            const bool more = (c + 1 < nc);
            if (more) { stage_w(sb, nb, cbase + c + 1, tid); CP_COMMIT(); }
            mma_chunk(sb, bb, acc, m0, h0, lane, ks0);
            if (more) build_z(smem, nb, layer, c + 1, tid);
            CP_WAIT0();
            __syncthreads();
        }

        // store acc -> h1s[n][h] (fp32)
        {
            const int r = lane >> 2;
            const int cc = (lane & 3) * 2;
            #pragma unroll
            for (int mt = 0; mt < 2; mt++)
                #pragma unroll
                for (int ht = 0; ht < 4; ht++) {
                    const int n = m0 + mt * 16 + r;
                    const int h = h0 + ht * 8 + cc;
                    *(float2*)&h1s[n * 132 + h] =
                        make_float2(acc[mt][ht][0], acc[mt][ht][1]);
                    *(float2*)&h1s[(n + 8) * 132 + h] =
                        make_float2(acc[mt][ht][2], acc[mt][ht][3]);
                }
        }
        __syncthreads();

        // out[b][h] = sum_d h1s[(bl*16+d)][h]
        const int obase = layer ? 128 : 0;
        #pragma unroll
        for (int rr = 0; rr < 2; rr++) {
            const int idx = rr * 512 + tid;
            const int bl = idx >> 7, h = idx & 127;
            float s = 0.f;
            #pragma unroll
            for (int d = 0; d < 16; d++) s += h1s[(bl * 16 + d) * 132 + h];
            out[(b0 + bl) * HOUT + obase + h] = s;
        }
        __syncthreads();
    }
}

extern "C" void kernel_launch(void* const* d_in, const int* in_sizes, int n_in,
                              void* d_out, int out_size) {
    const float* xin = (const float*)d_in[0];
    const float* W0  = (const float*)d_in[1];
    const float* W1  = (const float*)d_in[2];
    float* out = (float*)d_out;

    prep_w<<<(NCT * 8192 + 255) / 256, 256>>>(W0, W1);

    cudaFuncSetAttribute(cin_main, cudaFuncAttributeMaxDynamicSharedMemorySize, SMEM_TOTAL);
    cin_main<<<256, 512, SMEM_TOTAL>>>(xin, out);
}

// round 7
// speedup vs baseline: 1.5095x; 1.3505x over previous
#include <cuda_runtime.h>
#include <cuda_fp16.h>
#include <cstdint>

#define K1    1521
#define K2    4992
#define NC1   24            // 1536/64
#define NC2   78            // 4992/64
#define NCT   (NC1 + NC2)   // 102
#define F0n   39
#define Dn    16
#define HOUT  256

// per-buffer: z[16KB] whi[16KB] wlo[16KB]
#define BUF_SZ    49152
#define XS_OFF    98304                   // float xs[128][40]  (20480 B)
#define H1S_OFF   118784                  // float h1s[128][132] (67584 B)
#define SMEM_TOTAL 186368

// Pre-split weights fp16 hi/lo, [chunk][h(128)][kl(64)], zero-padded past K1.
__device__ __half g_Whi[NCT * 8192];
__device__ __half g_Wlo[NCT * 8192];

__device__ __forceinline__ uint32_t smem_u32(const void* p) {
    uint32_t a;
    asm("{ .reg .u64 t; cvta.to.shared.u64 t, %1; cvt.u32.u64 %0, t; }" : "=r"(a) : "l"(p));
    return a;
}

#define CP16(dst, src) \
    asm volatile("cp.async.cg.shared.global [%0], [%1], 16;" :: "r"(dst), "l"(src))
#define CP_COMMIT() asm volatile("cp.async.commit_group;" ::: "memory")
#define CP_WAIT0()  asm volatile("cp.async.wait_group 0;" ::: "memory")

#define LDSM_X4(r0, r1, r2, r3, addr) \
    asm volatile("ldmatrix.sync.aligned.m8n8.x4.shared.b16 {%0,%1,%2,%3}, [%4];" \
                 : "=r"(r0), "=r"(r1), "=r"(r2), "=r"(r3) : "r"(addr))

#define MMA16816H(d, a, b0_, b1_) \
    asm volatile("mma.sync.aligned.m16n8k16.row.col.f32.f16.f16.f32 " \
                 "{%0,%1,%2,%3}, {%4,%5,%6,%7}, {%8,%9}, {%0,%1,%2,%3};" \
                 : "+f"((d)[0]), "+f"((d)[1]), "+f"((d)[2]), "+f"((d)[3]) \
                 : "r"((a)[0]), "r"((a)[1]), "r"((a)[2]), "r"((a)[3]), \
                   "r"(b0_), "r"(b1_))

// ---------------- weight prep: split hi/lo fp16 ----------------
__global__ void prep_w(const float* __restrict__ W0, const float* __restrict__ W1) {
    int idx = blockIdx.x * 256 + threadIdx.x;
    if (idx >= NCT * 8192) return;
    int chunk = idx >> 13;
    int h = (idx >> 6) & 127;
    int kl = idx & 63;
    float w = 0.f;
    if (chunk < NC1) {
        int k = chunk * 64 + kl;
        if (k < K1) w = W0[h * K1 + k];
    } else {
        int k = (chunk - NC1) * 64 + kl;
        w = W1[h * K2 + k];
    }
    __half hi = __float2half_rn(w);
    __half lo = __float2half_rn(w - __half2float(hi));
    g_Whi[idx] = hi;
    g_Wlo[idx] = lo;
}

// ---------------- device helpers ----------------
__device__ __forceinline__ void stage_w(uint32_t sb, int bb, int chunk, int tid) {
    const uint32_t wbase = sb + bb * BUF_SZ + 16384;
    #pragma unroll
    for (int t = 0; t < 4; t++) {
        int i = tid + t * 512;            // 0..2047
        int tile = i >> 10;               // 0=hi, 1=lo
        int h = (i >> 3) & 127;
        int seg = i & 7;
        const __half* src = (tile ? g_Wlo : g_Whi) + chunk * 8192 + h * 64 + seg * 8;
        uint32_t dst = wbase + tile * 16384 + h * 128 + ((seg * 16) ^ ((h & 7) << 4));
        CP16(dst, src);
    }
}

// z-build: thread owns kl-pair x 8 n-rows -> single fp16 tile, STS.32
__device__ __forceinline__ void build_z(char* smem, int bb, int layer, int c, int tid) {
    const float* xs  = (const float*)(smem + XS_OFF);
    const float* h1s = (const float*)(smem + H1S_OFF);
    char* zt = smem + bb * BUF_SZ;
    const int klp = (tid & 31) * 2;
    const int n0  = (tid >> 5) * 8;
    int f0 = 0, q0 = 0, f1 = 0, q1 = 0;
    bool v0 = true, v1 = true;
    {
        const int k0 = c * 64 + klp, k1_ = k0 + 1;
        if (layer == 0) {
            if (k0 < K1) { f0 = k0 / 39; q0 = k0 - f0 * 39; } else v0 = false;
            if (k1_ < K1) { f1 = k1_ / 39; q1 = k1_ - f1 * 39; } else v1 = false;
        } else {
            f0 = k0 >> 7; q0 = k0 & 127;
            f1 = k1_ >> 7; q1 = k1_ & 127;
        }
    }
    const int bstride = layer ? 132 : 40;
    const float* bbase = layer ? h1s : xs;
    const uint32_t cb = (uint32_t)(klp * 2);
    #pragma unroll
    for (int nn = 0; nn < 8; nn++) {
        const int n = n0 + nn;
        float z0 = v0 ? xs[n * 40 + f0] * bbase[n * bstride + q0] : 0.f;
        float z1 = v1 ? xs[n * 40 + f1] * bbase[n * bstride + q1] : 0.f;
        __half2 hv = __floats2half2_rn(z0, z1);
        uint32_t off = (uint32_t)(n * 128) + (cb ^ ((uint32_t)(n & 7) << 4));
        *(__half2*)(zt + off) = hv;
    }
}

__device__ __forceinline__ void load_frags(
    int kb, const uint32_t adb[2], const uint32_t asw[2],
    const uint32_t bdb[2], const uint32_t bsw[2],
    uint32_t aselb, uint32_t bselb,
    uint32_t A[2][4], uint32_t BH[8], uint32_t BL[8])
{
    const uint32_t kb2 = (uint32_t)(kb * 2);
    #pragma unroll
    for (int mt = 0; mt < 2; mt++) {
        uint32_t ad = adb[mt] + ((kb2 + aselb) ^ asw[mt]);
        LDSM_X4(A[mt][0], A[mt][1], A[mt][2], A[mt][3], ad);
    }
    #pragma unroll
    for (int pr = 0; pr < 2; pr++) {
        uint32_t bd = bdb[pr] + ((kb2 + bselb) ^ bsw[pr]);
        LDSM_X4(BH[pr * 4 + 0], BH[pr * 4 + 1], BH[pr * 4 + 2], BH[pr * 4 + 3], bd);
        LDSM_X4(BL[pr * 4 + 0], BL[pr * 4 + 1], BL[pr * 4 + 2], BL[pr * 4 + 3], bd + 16384);
    }
}

// MMA over chunk bb; ks rotated per warp; cross-kstep fragment ping-pong
__device__ __forceinline__ void mma_chunk(uint32_t sb, int bb, float acc[2][4][4],
                                          int m0, int h0, int lane, int ks0) {
    const uint32_t zb = sb + bb * BUF_SZ;
    const uint32_t wb = zb + 16384;
    uint32_t adb[2], asw[2], bdb[2], bsw[2];
    #pragma unroll
    for (int mt = 0; mt < 2; mt++) {
        const int n = m0 + mt * 16 + (lane & 15);
        adb[mt] = zb + n * 128;
        asw[mt] = (uint32_t)(n & 7) << 4;
    }
    #pragma unroll
    for (int pr = 0; pr < 2; pr++) {
        const int h = h0 + pr * 16 + (lane >> 4) * 8 + (lane & 7);
        bdb[pr] = wb + h * 128;
        bsw[pr] = (uint32_t)(h & 7) << 4;
    }
    const uint32_t aselb = (uint32_t)((lane >> 4) * 16);
    const uint32_t bselb = (uint32_t)(((lane >> 3) & 1) * 16);

    uint32_t A[2][2][4], BH[2][8], BL[2][8];
    load_frags((ks0 & 3) * 16, adb, asw, bdb, bsw, aselb, bselb, A[0], BH[0], BL[0]);
    #pragma unroll
    for (int kk = 0; kk < 4; kk++) {
        const int cur = kk & 1;
        const int nxt = cur ^ 1;
        if (kk < 3)
            load_frags(((kk + 1 + ks0) & 3) * 16, adb, asw, bdb, bsw, aselb, bselb,
                       A[nxt], BH[nxt], BL[nxt]);
        #pragma unroll
        for (int mt = 0; mt < 2; mt++)
            #pragma unroll
            for (int ht = 0; ht < 4; ht++)
                MMA16816H(acc[mt][ht], A[cur][mt], BH[cur][ht * 2], BH[cur][ht * 2 + 1]);
        #pragma unroll
        for (int mt = 0; mt < 2; mt++)
            #pragma unroll
            for (int ht = 0; ht < 4; ht++)
                MMA16816H(acc[mt][ht], A[cur][mt], BL[cur][ht * 2], BL[cur][ht * 2 + 1]);
    }
}

// ---------------- main kernel ----------------
__global__ __launch_bounds__(512, 1)
void cin_main(const float* __restrict__ x, float* __restrict__ out) {
    extern __shared__ __align__(1024) char smem[];
    const uint32_t sb = smem_u32(smem);
    float* xs  = (float*)(smem + XS_OFF);
    float* h1s = (float*)(smem + H1S_OFF);

    const int tid = threadIdx.x;
    const int lane = tid & 31;
    const int warp = tid >> 5;
    const int m0 = (warp & 3) * 32;
    const int h0 = (warp >> 2) * 32;
    const int ks0 = warp & 3;
    const int b0 = blockIdx.x * 8;

    for (int i = tid; i < F0n * 128; i += 512) {
        int f = i >> 7, c = i & 127;
        int b = b0 + (c >> 4), d = c & 15;
        xs[c * 40 + f] = x[(b * F0n + f) * Dn + d];
    }
    __syncthreads();

    float acc[2][4][4];

    #pragma unroll 1
    for (int layer = 0; layer < 2; layer++) {
        const int nc = layer ? NC2 : NC1;
        const int cbase = layer ? NC1 : 0;

        #pragma unroll
        for (int mt = 0; mt < 2; mt++)
            #pragma unroll
            for (int ht = 0; ht < 4; ht++)
                #pragma unroll
                for (int j = 0; j < 4; j++) acc[mt][ht][j] = 0.f;

        stage_w(sb, 0, cbase, tid);
        CP_COMMIT();
        build_z(smem, 0, layer, 0, tid);
        CP_WAIT0();
        __syncthreads();

        #pragma unroll 1
        for (int c = 0; c < nc; c++) {
            const int bb = c & 1;
            const int nb = bb ^ 1;
            const bool more = (c + 1 < nc);
            if (more) { stage_w(sb, nb, cbase + c + 1, tid); CP_COMMIT(); }
            mma_chunk(sb, bb, acc, m0, h0, lane, ks0);
            if (more) build_z(smem, nb, layer, c + 1, tid);
            CP_WAIT0();
            __syncthreads();
        }

        // store acc -> h1s[n][h] (fp32)
        {
            const int r = lane >> 2;
            const int cc = (lane & 3) * 2;
            #pragma unroll
            for (int mt = 0; mt < 2; mt++)
                #pragma unroll
                for (int ht = 0; ht < 4; ht++) {
                    const int n = m0 + mt * 16 + r;
                    const int h = h0 + ht * 8 + cc;
                    *(float2*)&h1s[n * 132 + h] =
                        make_float2(acc[mt][ht][0], acc[mt][ht][1]);
                    *(float2*)&h1s[(n + 8) * 132 + h] =
                        make_float2(acc[mt][ht][2], acc[mt][ht][3]);
                }
        }
        __syncthreads();

        // out[b][h] = sum_d h1s[(bl*16+d)][h]
        const int obase = layer ? 128 : 0;
        #pragma unroll
        for (int rr = 0; rr < 2; rr++) {
            const int idx = rr * 512 + tid;
            const int bl = idx >> 7, h = idx & 127;
            float s = 0.f;
            #pragma unroll
            for (int d = 0; d < 16; d++) s += h1s[(bl * 16 + d) * 132 + h];
            out[(b0 + bl) * HOUT + obase + h] = s;
        }
        __syncthreads();
    }
}

extern "C" void kernel_launch(void* const* d_in, const int* in_sizes, int n_in,
                              void* d_out, int out_size) {
    const float* xin = (const float*)d_in[0];
    const float* W0  = (const float*)d_in[1];
    const float* W1  = (const float*)d_in[2];
    float* out = (float*)d_out;

    prep_w<<<(NCT * 8192 + 255) / 256, 256>>>(W0, W1);

    cudaFuncSetAttribute(cin_main, cudaFuncAttributeMaxDynamicSharedMemorySize, SMEM_TOTAL);
    cin_main<<<256, 512, SMEM_TOTAL>>>(xin, out);
}

// round 8
// speedup vs baseline: 2.1881x; 1.4496x over previous
#include <cuda_runtime.h>
#include <cuda_fp16.h>
#include <cstdint>

#define K1    1521
#define K2    4992
#define NC1   24            // 1536/64
#define NC2   78            // 4992/64
#define NCT   (NC1 + NC2)   // 102
#define F0n   39
#define Dn    16
#define HOUT  256

// 4 buffers x 32KB: z[16KB] + W[16KB]
#define BUF_SZ    32768
#define XS_OFF    131072                  // float xs[128][40]   (20480 B)
#define H1S_OFF   151552                  // float h1s[128][132] (67584 B)
#define SMEM_TOTAL 219136

// Single fp16 weights, [chunk][h(128)][kl(64)], zero-padded past K1.
__device__ __half g_W[NCT * 8192];

__device__ __forceinline__ uint32_t smem_u32(const void* p) {
    uint32_t a;
    asm("{ .reg .u64 t; cvta.to.shared.u64 t, %1; cvt.u32.u64 %0, t; }" : "=r"(a) : "l"(p));
    return a;
}

#define CP16(dst, src) \
    asm volatile("cp.async.cg.shared.global [%0], [%1], 16;" :: "r"(dst), "l"(src))
#define CP_COMMIT() asm volatile("cp.async.commit_group;" ::: "memory")
#define CP_WAIT0()  asm volatile("cp.async.wait_group 0;" ::: "memory")

#define LDSM_X4(r0, r1, r2, r3, addr) \
    asm volatile("ldmatrix.sync.aligned.m8n8.x4.shared.b16 {%0,%1,%2,%3}, [%4];" \
                 : "=r"(r0), "=r"(r1), "=r"(r2), "=r"(r3) : "r"(addr))

#define MMA16816H(d, a, b0_, b1_) \
    asm volatile("mma.sync.aligned.m16n8k16.row.col.f32.f16.f16.f32 " \
                 "{%0,%1,%2,%3}, {%4,%5,%6,%7}, {%8,%9}, {%0,%1,%2,%3};" \
                 : "+f"((d)[0]), "+f"((d)[1]), "+f"((d)[2]), "+f"((d)[3]) \
                 : "r"((a)[0]), "r"((a)[1]), "r"((a)[2]), "r"((a)[3]), \
                   "r"(b0_), "r"(b1_))

// ---------------- weight prep: fp16 ----------------
__global__ void prep_w(const float* __restrict__ W0, const float* __restrict__ W1) {
    int idx = blockIdx.x * 256 + threadIdx.x;
    if (idx >= NCT * 8192) return;
    int chunk = idx >> 13;
    int h = (idx >> 6) & 127;
    int kl = idx & 63;
    float w = 0.f;
    if (chunk < NC1) {
        int k = chunk * 64 + kl;
        if (k < K1) w = W0[h * K1 + k];
    } else {
        int k = (chunk - NC1) * 64 + kl;
        w = W1[h * K2 + k];
    }
    g_W[idx] = __float2half_rn(w);
}

// ---------------- device helpers ----------------
__device__ __forceinline__ void stage_w(uint32_t sb, int buf, int chunk, int tid) {
    const uint32_t wbase = sb + buf * BUF_SZ + 16384;
    #pragma unroll
    for (int t = 0; t < 2; t++) {
        int i = tid + t * 512;            // 0..1023
        int h = i >> 3;
        int seg = i & 7;
        const __half* src = g_W + chunk * 8192 + h * 64 + seg * 8;
        uint32_t dst = wbase + h * 128 + ((seg * 16) ^ ((h & 7) << 4));
        CP16(dst, src);
    }
}

// z-build: thread owns kl-pair x 8 n-rows -> fp16 tile, STS.32
__device__ __forceinline__ void build_z(char* smem, int buf, int layer, int c, int tid) {
    const float* xs  = (const float*)(smem + XS_OFF);
    const float* h1s = (const float*)(smem + H1S_OFF);
    char* zt = smem + buf * BUF_SZ;
    const int klp = (tid & 31) * 2;
    const int n0  = (tid >> 5) * 8;
    int f0 = 0, q0 = 0, f1 = 0, q1 = 0;
    bool v0 = true, v1 = true;
    {
        const int k0 = c * 64 + klp, k1_ = k0 + 1;
        if (layer == 0) {
            if (k0 < K1) { f0 = k0 / 39; q0 = k0 - f0 * 39; } else v0 = false;
            if (k1_ < K1) { f1 = k1_ / 39; q1 = k1_ - f1 * 39; } else v1 = false;
        } else {
            f0 = k0 >> 7; q0 = k0 & 127;
            f1 = k1_ >> 7; q1 = k1_ & 127;
        }
    }
    const int bstride = layer ? 132 : 40;
    const float* bbase = layer ? h1s : xs;
    const uint32_t cb = (uint32_t)(klp * 2);
    #pragma unroll
    for (int nn = 0; nn < 8; nn++) {
        const int n = n0 + nn;
        float z0 = v0 ? xs[n * 40 + f0] * bbase[n * bstride + q0] : 0.f;
        float z1 = v1 ? xs[n * 40 + f1] * bbase[n * bstride + q1] : 0.f;
        __half2 hv = __floats2half2_rn(z0, z1);
        uint32_t off = (uint32_t)(n * 128) + (cb ^ ((uint32_t)(n & 7) << 4));
        *(__half2*)(zt + off) = hv;
    }
}

__device__ __forceinline__ void load_frags(
    int kb, const uint32_t adb[2], const uint32_t asw[2],
    const uint32_t bdb[2], const uint32_t bsw[2],
    uint32_t aselb, uint32_t bselb,
    uint32_t A[2][4], uint32_t B[8])
{
    const uint32_t kb2 = (uint32_t)(kb * 2);
    #pragma unroll
    for (int mt = 0; mt < 2; mt++) {
        uint32_t ad = adb[mt] + ((kb2 + aselb) ^ asw[mt]);
        LDSM_X4(A[mt][0], A[mt][1], A[mt][2], A[mt][3], ad);
    }
    #pragma unroll
    for (int pr = 0; pr < 2; pr++) {
        uint32_t bd = bdb[pr] + ((kb2 + bselb) ^ bsw[pr]);
        LDSM_X4(B[pr * 4 + 0], B[pr * 4 + 1], B[pr * 4 + 2], B[pr * 4 + 3], bd);
    }
}

// MMA over one chunk buffer; ks rotated per warp; cross-kstep fragment ping-pong
__device__ __forceinline__ void mma_chunk(uint32_t sb, int buf, float acc[2][4][4],
                                          int m0, int h0, int lane, int ks0) {
    const uint32_t zb = sb + buf * BUF_SZ;
    const uint32_t wb = zb + 16384;
    uint32_t adb[2], asw[2], bdb[2], bsw[2];
    #pragma unroll
    for (int mt = 0; mt < 2; mt++) {
        const int n = m0 + mt * 16 + (lane & 15);
        adb[mt] = zb + n * 128;
        asw[mt] = (uint32_t)(n & 7) << 4;
    }
    #pragma unroll
    for (int pr = 0; pr < 2; pr++) {
        const int h = h0 + pr * 16 + (lane >> 4) * 8 + (lane & 7);
        bdb[pr] = wb + h * 128;
        bsw[pr] = (uint32_t)(h & 7) << 4;
    }
    const uint32_t aselb = (uint32_t)((lane >> 4) * 16);
    const uint32_t bselb = (uint32_t)(((lane >> 3) & 1) * 16);

    uint32_t A[2][2][4], B[2][8];
    load_frags((ks0 & 3) * 16, adb, asw, bdb, bsw, aselb, bselb, A[0], B[0]);
    #pragma unroll
    for (int kk = 0; kk < 4; kk++) {
        const int cur = kk & 1;
        const int nxt = cur ^ 1;
        if (kk < 3)
            load_frags(((kk + 1 + ks0) & 3) * 16, adb, asw, bdb, bsw, aselb, bselb,
                       A[nxt], B[nxt]);
        #pragma unroll
        for (int mt = 0; mt < 2; mt++)
            #pragma unroll
            for (int ht = 0; ht < 4; ht++)
                MMA16816H(acc[mt][ht], A[cur][mt], B[cur][ht * 2], B[cur][ht * 2 + 1]);
    }
}

// ---------------- main kernel ----------------
__global__ __launch_bounds__(512, 1)
void cin_main(const float* __restrict__ x, float* __restrict__ out) {
    extern __shared__ __align__(1024) char smem[];
    const uint32_t sb = smem_u32(smem);
    float* xs  = (float*)(smem + XS_OFF);
    float* h1s = (float*)(smem + H1S_OFF);

    const int tid = threadIdx.x;
    const int lane = tid & 31;
    const int warp = tid >> 5;
    const int m0 = (warp & 3) * 32;
    const int h0 = (warp >> 2) * 32;
    const int ks0 = warp & 3;
    const int b0 = blockIdx.x * 8;

    for (int i = tid; i < F0n * 128; i += 512) {
        int f = i >> 7, c = i & 127;
        int b = b0 + (c >> 4), d = c & 15;
        xs[c * 40 + f] = x[(b * F0n + f) * Dn + d];
    }
    __syncthreads();

    float acc[2][4][4];

    #pragma unroll 1
    for (int layer = 0; layer < 2; layer++) {
        const int nc = layer ? NC2 : NC1;      // both even
        const int cbase = layer ? NC1 : 0;

        #pragma unroll
        for (int mt = 0; mt < 2; mt++)
            #pragma unroll
            for (int ht = 0; ht < 4; ht++)
                #pragma unroll
                for (int j = 0; j < 4; j++) acc[mt][ht][j] = 0.f;

        // prologue: stage + build chunks 0,1
        stage_w(sb, 0, cbase, tid);
        stage_w(sb, 1, cbase + 1, tid);
        CP_COMMIT();
        build_z(smem, 0, layer, 0, tid);
        build_z(smem, 1, layer, 1, tid);
        CP_WAIT0();
        __syncthreads();

        #pragma unroll 1
        for (int c = 0; c < nc; c += 2) {
            const bool more = (c + 2 < nc);
            if (more) {
                stage_w(sb, (c + 2) & 3, cbase + c + 2, tid);
                stage_w(sb, (c + 3) & 3, cbase + c + 3, tid);
                CP_COMMIT();
            }
            mma_chunk(sb, c & 3, acc, m0, h0, lane, ks0);
            if (more) build_z(smem, (c + 2) & 3, layer, c + 2, tid);
            mma_chunk(sb, (c + 1) & 3, acc, m0, h0, lane, ks0);
            if (more) build_z(smem, (c + 3) & 3, layer, c + 3, tid);
            CP_WAIT0();
            __syncthreads();
        }

        // store acc -> h1s[n][h] (fp32)
        {
            const int r = lane >> 2;
            const int cc = (lane & 3) * 2;
            #pragma unroll
            for (int mt = 0; mt < 2; mt++)
                #pragma unroll
                for (int ht = 0; ht < 4; ht++) {
                    const int n = m0 + mt * 16 + r;
                    const int h = h0 + ht * 8 + cc;
                    *(float2*)&h1s[n * 132 + h] =
                        make_float2(acc[mt][ht][0], acc[mt][ht][1]);
                    *(float2*)&h1s[(n + 8) * 132 + h] =
                        make_float2(acc[mt][ht][2], acc[mt][ht][3]);
                }
        }
        __syncthreads();

        // out[b][h] = sum_d h1s[(bl*16+d)][h]
        const int obase = layer ? 128 : 0;
        #pragma unroll
        for (int rr = 0; rr < 2; rr++) {
            const int idx = rr * 512 + tid;
            const int bl = idx >> 7, h = idx & 127;
            float s = 0.f;
            #pragma unroll
            for (int d = 0; d < 16; d++) s += h1s[(bl * 16 + d) * 132 + h];
            out[(b0 + bl) * HOUT + obase + h] = s;
        }
        __syncthreads();
    }
}

extern "C" void kernel_launch(void* const* d_in, const int* in_sizes, int n_in,
                              void* d_out, int out_size) {
    const float* xin = (const float*)d_in[0];
    const float* W0  = (const float*)d_in[1];
    const float* W1  = (const float*)d_in[2];
    float* out = (float*)d_out;

    prep_w<<<(NCT * 8192 + 255) / 256, 256>>>(W0, W1);

    cudaFuncSetAttribute(cin_main, cudaFuncAttributeMaxDynamicSharedMemorySize, SMEM_TOTAL);
    cin_main<<<256, 512, SMEM_TOTAL>>>(xin, out);
}

// round 10
// speedup vs baseline: 2.6532x; 1.2125x over previous
#include <cuda_runtime.h>
#include <cuda_fp16.h>
#include <cstdint>

#define F0n   39
#define Dn    16
#define HOUT  256
#define K1    1521
#define K2    4992
#define NF1   40        // L1 f-chunks (39 valid + 1 zero)
#define NC2   156       // L2 chunks: 4 q-quarters x 39 f

#define SLOT_SZ    16384
#define XS_OFF     65536                 // float xs[128][40]   20480 B
#define H1S_OFF    86016                 // float h1s[128][132] 67584 B
#define SMEM_TOTAL 153600

// L1 weights: [f][128h][64k] fp16 (k 0..38 valid, rest 0), 128B rows, XOR-swizzled
__device__ __half g_W1c[NF1 * 8192];
// L2 weights: [qq*39+f][64 rows][64 halves] split-row (h,h+64 share a 128B row), swizzled
__device__ __half g_W2c[NC2 * 4096];

__device__ __forceinline__ uint32_t smem_u32(const void* p) {
    uint32_t a;
    asm("{ .reg .u64 t; cvta.to.shared.u64 t, %1; cvt.u32.u64 %0, t; }" : "=r"(a) : "l"(p));
    return a;
}
__device__ __forceinline__ uint32_t pack_h2(float lo, float hi) {
    uint32_t r_;
    asm("cvt.rn.f16x2.f32 %0, %1, %2;" : "=r"(r_) : "f"(hi), "f"(lo));
    return r_;
}

#define CP16(dst, src) \
    asm volatile("cp.async.cg.shared.global [%0], [%1], 16;" :: "r"(dst), "l"(src))
#define CP_COMMIT() asm volatile("cp.async.commit_group;" ::: "memory")
#define CP_WAIT0()  asm volatile("cp.async.wait_group 0;" ::: "memory")
#define CP_WAIT1()  asm volatile("cp.async.wait_group 1;" ::: "memory")

#define LDSM_X4(r0, r1, r2, r3, addr) \
    asm volatile("ldmatrix.sync.aligned.m8n8.x4.shared.b16 {%0,%1,%2,%3}, [%4];" \
                 : "=r"(r0), "=r"(r1), "=r"(r2), "=r"(r3) : "r"(addr))

#define MMA16816H(d, a, b0_, b1_) \
    asm volatile("mma.sync.aligned.m16n8k16.row.col.f32.f16.f16.f32 " \
                 "{%0,%1,%2,%3}, {%4,%5,%6,%7}, {%8,%9}, {%0,%1,%2,%3};" \
                 : "+f"((d)[0]), "+f"((d)[1]), "+f"((d)[2]), "+f"((d)[3]) \
                 : "r"((a)[0]), "r"((a)[1]), "r"((a)[2]), "r"((a)[3]), \
                   "r"(b0_), "r"(b1_))

// ---------------- weight prep ----------------
__global__ void prep_w1(const float* __restrict__ W0) {
    int idx = blockIdx.x * 256 + threadIdx.x;
    if (idx >= NF1 * 8192) return;
    int f  = idx >> 13;
    int h  = (idx >> 6) & 127;
    int kl = idx & 63;
    float w = (f < F0n && kl < F0n) ? W0[h * K1 + f * F0n + kl] : 0.f;
    uint32_t byte = (uint32_t)h * 128 + (((uint32_t)kl * 2) ^ ((uint32_t)(h & 7) << 4));
    g_W1c[f * 8192 + (byte >> 1)] = __float2half_rn(w);
}
__global__ void prep_w2(const float* __restrict__ W1) {
    int idx = blockIdx.x * 256 + threadIdx.x;
    if (idx >= NC2 * 4096) return;
    int ci  = idx >> 12;
    int h   = (idx >> 5) & 127;
    int kl  = idx & 31;
    int qq  = ci / 39;
    int f   = ci - qq * 39;
    float w = W1[h * K2 + f * 128 + qq * 32 + kl];
    uint32_t byte = (uint32_t)(h & 63) * 128 +
        ((((uint32_t)(h >> 6) * 64) + (uint32_t)kl * 2) ^ ((uint32_t)(h & 7) << 4));
    g_W2c[ci * 4096 + (byte >> 1)] = __float2half_rn(w);
}

// ---------------- staging ----------------
__device__ __forceinline__ void stage_l1(uint32_t sb, int slot, int f, int tid) {
    const uint32_t base = sb + slot * SLOT_SZ;
    const __half* src = g_W1c + f * 8192;
    CP16(base + tid * 16, src + tid * 8);
    CP16(base + (tid + 512) * 16, src + (tid + 512) * 8);
}
__device__ __forceinline__ void stage_l2(uint32_t sb, int slot, int ci, int tid) {
    const uint32_t base = sb + slot * SLOT_SZ;
    const __half* src = g_W2c + ci * 4096;
    CP16(base + tid * 16, src + tid * 8);
}

// ---------------- MMA bodies ----------------
__device__ __forceinline__ void mma_l1(
    uint32_t sb, const float* xs, int slot, int f,
    const float xa[2][3][8], float acc[2][4][4],
    int m0, int r, const uint32_t bRow1[2], const uint32_t bXor[2], uint32_t bSel)
{
    const uint32_t wb = sb + slot * SLOT_SZ;
    float xr[2][2];
    #pragma unroll
    for (int mt = 0; mt < 2; mt++) {
        xr[mt][0] = xs[(m0 + mt * 16 + r) * 40 + f];
        xr[mt][1] = xs[(m0 + mt * 16 + r + 8) * 40 + f];
    }
    #pragma unroll
    for (int ks = 0; ks < 3; ks++) {
        uint32_t B[8];
        #pragma unroll
        for (int pr = 0; pr < 2; pr++) {
            uint32_t bd = wb + bRow1[pr] + (((uint32_t)(ks * 32) + bSel) ^ bXor[pr]);
            LDSM_X4(B[pr * 4 + 0], B[pr * 4 + 1], B[pr * 4 + 2], B[pr * 4 + 3], bd);
        }
        #pragma unroll
        for (int mt = 0; mt < 2; mt++) {
            uint32_t A[4];
            A[0] = pack_h2(xr[mt][0] * xa[mt][ks][0], xr[mt][0] * xa[mt][ks][1]);
            A[1] = pack_h2(xr[mt][1] * xa[mt][ks][2], xr[mt][1] * xa[mt][ks][3]);
            A[2] = pack_h2(xr[mt][0] * xa[mt][ks][4], xr[mt][0] * xa[mt][ks][5]);
            A[3] = pack_h2(xr[mt][1] * xa[mt][ks][6], xr[mt][1] * xa[mt][ks][7]);
            #pragma unroll
            for (int ht = 0; ht < 4; ht++)
                MMA16816H(acc[mt][ht], A, B[ht * 2], B[ht * 2 + 1]);
        }
    }
}

__device__ __forceinline__ void load_res_l2(const float* h1s, float hv[2][2][8],
                                            int qq, int m0, int r, int c2) {
    #pragma unroll
    for (int mt = 0; mt < 2; mt++) {
        const int n = m0 + mt * 16 + r;
        #pragma unroll
        for (int ks = 0; ks < 2; ks++) {
            const int q0 = qq * 32 + ks * 16 + c2;
            hv[mt][ks][0] = h1s[n * 132 + q0];
            hv[mt][ks][1] = h1s[n * 132 + q0 + 1];
            hv[mt][ks][2] = h1s[(n + 8) * 132 + q0];
            hv[mt][ks][3] = h1s[(n + 8) * 132 + q0 + 1];
            hv[mt][ks][4] = h1s[n * 132 + q0 + 8];
            hv[mt][ks][5] = h1s[n * 132 + q0 + 9];
            hv[mt][ks][6] = h1s[(n + 8) * 132 + q0 + 8];
            hv[mt][ks][7] = h1s[(n + 8) * 132 + q0 + 9];
        }
    }
}

__device__ __forceinline__ void mma_l2(
    uint32_t sb, const float* xs, int slot, int f,
    const float hv[2][2][8], float acc[2][4][4],
    int m0, int r, const uint32_t bRow2[2], const uint32_t bHalf[2],
    const uint32_t bXor[2], uint32_t bSel)
{
    const uint32_t wb = sb + slot * SLOT_SZ;
    float xr[2][2];
    #pragma unroll
    for (int mt = 0; mt < 2; mt++) {
        xr[mt][0] = xs[(m0 + mt * 16 + r) * 40 + f];
        xr[mt][1] = xs[(m0 + mt * 16 + r + 8) * 40 + f];
    }
    #pragma unroll
    for (int ks = 0; ks < 2; ks++) {
        uint32_t B[8];
        #pragma unroll
        for (int pr = 0; pr < 2; pr++) {
            uint32_t bd = wb + bRow2[pr] +
                ((bHalf[pr] + (uint32_t)(ks * 32) + bSel) ^ bXor[pr]);
            LDSM_X4(B[pr * 4 + 0], B[pr * 4 + 1], B[pr * 4 + 2], B[pr * 4 + 3], bd);
        }
        #pragma unroll
        for (int mt = 0; mt < 2; mt++) {
            uint32_t A[4];
            A[0] = pack_h2(xr[mt][0] * hv[mt][ks][0], xr[mt][0] * hv[mt][ks][1]);
            A[1] = pack_h2(xr[mt][1] * hv[mt][ks][2], xr[mt][1] * hv[mt][ks][3]);
            A[2] = pack_h2(xr[mt][0] * hv[mt][ks][4], xr[mt][0] * hv[mt][ks][5]);
            A[3] = pack_h2(xr[mt][1] * hv[mt][ks][6], xr[mt][1] * hv[mt][ks][7]);
            #pragma unroll
            for (int ht = 0; ht < 4; ht++)
                MMA16816H(acc[mt][ht], A, B[ht * 2], B[ht * 2 + 1]);
        }
    }
}

// ---------------- main kernel ----------------
__global__ __launch_bounds__(512, 1)
void cin_main(const float* __restrict__ x, float* __restrict__ out) {
    extern __shared__ __align__(1024) char smem[];
    const uint32_t sb = smem_u32(smem);
    float* xs  = (float*)(smem + XS_OFF);
    float* h1s = (float*)(smem + H1S_OFF);

    const int tid  = threadIdx.x;
    const int lane = tid & 31;
    const int warp = tid >> 5;
    const int m0 = (warp & 3) * 32;
    const int h0 = (warp >> 2) * 32;
    const int b0 = blockIdx.x * 8;
    const int r  = lane >> 2;
    const int c2 = (lane & 3) * 2;

    uint32_t bXor[2], bRow1[2], bRow2[2], bHalf[2];
    #pragma unroll
    for (int pr = 0; pr < 2; pr++) {
        int hB = h0 + pr * 16 + (lane >> 4) * 8 + (lane & 7);
        bXor[pr]  = (uint32_t)(hB & 7) << 4;
        bRow1[pr] = (uint32_t)hB * 128;
        bRow2[pr] = (uint32_t)(hB & 63) * 128;
        bHalf[pr] = (uint32_t)(hB >> 6) * 64;
    }
    const uint32_t bSel = (uint32_t)((lane >> 3) & 1) * 16;

    // prefetch L1 chunks 0..3 (overlaps with xs fill)
    stage_l1(sb, 0, 0, tid); stage_l1(sb, 1, 1, tid); CP_COMMIT();
    stage_l1(sb, 2, 2, tid); stage_l1(sb, 3, 3, tid); CP_COMMIT();

    // xs[n][f], n = (b_local<<4)|d ; col 39 zeroed (used when f-chunk 39 pads)
    for (int i = tid; i < F0n * 128; i += 512) {
        int f = i >> 7, cc = i & 127;
        int b = b0 + (cc >> 4), d = cc & 15;
        xs[cc * 40 + f] = x[(b * F0n + f) * Dn + d];
    }
    for (int i = tid; i < 128; i += 512) xs[i * 40 + 39] = 0.f;
    CP_WAIT1();
    __syncthreads();

    float acc[2][4][4];
    #pragma unroll
    for (int mt = 0; mt < 2; mt++)
        #pragma unroll
        for (int ht = 0; ht < 4; ht++)
            #pragma unroll
            for (int j = 0; j < 4; j++) acc[mt][ht][j] = 0.f;

    // ================= Layer 1 =================
    {
        // resident x fragments (q = 0..47, guarded)
        float xa[2][3][8];
        #pragma unroll
        for (int mt = 0; mt < 2; mt++) {
            const int n = m0 + mt * 16 + r;
            #pragma unroll
            for (int ks = 0; ks < 3; ks++) {
                const int q0 = ks * 16 + c2;
                xa[mt][ks][0] = (q0     < F0n) ? xs[n * 40 + q0]           : 0.f;
                xa[mt][ks][1] = (q0 + 1 < F0n) ? xs[n * 40 + q0 + 1]       : 0.f;
                xa[mt][ks][2] = (q0     < F0n) ? xs[(n + 8) * 40 + q0]     : 0.f;
                xa[mt][ks][3] = (q0 + 1 < F0n) ? xs[(n + 8) * 40 + q0 + 1] : 0.f;
                xa[mt][ks][4] = (q0 + 8 < F0n) ? xs[n * 40 + q0 + 8]       : 0.f;
                xa[mt][ks][5] = (q0 + 9 < F0n) ? xs[n * 40 + q0 + 9]       : 0.f;
                xa[mt][ks][6] = (q0 + 8 < F0n) ? xs[(n + 8) * 40 + q0 + 8] : 0.f;
                xa[mt][ks][7] = (q0 + 9 < F0n) ? xs[(n + 8) * 40 + q0 + 9] : 0.f;
            }
        }

        #pragma unroll 1
        for (int cc = 0; cc < NF1; cc += 2) {
            mma_l1(sb, xs, cc & 3, cc, xa, acc, m0, r, bRow1, bXor, bSel);
            mma_l1(sb, xs, (cc + 1) & 3, cc + 1, xa, acc, m0, r, bRow1, bXor, bSel);
            CP_WAIT0();
            __syncthreads();
            if (cc + 4 < NF1) {
                stage_l1(sb, (cc + 4) & 3, cc + 4, tid);
                stage_l1(sb, (cc + 5) & 3, cc + 5, tid);
                CP_COMMIT();
            } else if (cc + 4 == NF1) {
                // Prefetch L2 chunks 0,1 into slots 0,1 ONLY — slots 2,3 still
                // hold L1 chunks 38,39 (consumed next iteration). Slots 2,3 are
                // restaged in the L1 epilogue below.
                stage_l2(sb, 0, 0, tid); stage_l2(sb, 1, 1, tid); CP_COMMIT();
            }
        }
    }

    // L1 epilogue: acc -> h1s fp32 (feeds L2 resident + out1)
    #pragma unroll
    for (int mt = 0; mt < 2; mt++)
        #pragma unroll
        for (int ht = 0; ht < 4; ht++) {
            const int n = m0 + mt * 16 + r;
            const int h = h0 + ht * 8 + c2;
            *(float2*)&h1s[n * 132 + h] = make_float2(acc[mt][ht][0], acc[mt][ht][1]);
            *(float2*)&h1s[(n + 8) * 132 + h] = make_float2(acc[mt][ht][2], acc[mt][ht][3]);
        }
    // now that L1 chunks 38,39 are fully consumed, restage slots 2,3 with L2
    stage_l2(sb, 2, 2, tid); stage_l2(sb, 3, 3, tid); CP_COMMIT();
    __syncthreads();
    #pragma unroll
    for (int rr = 0; rr < 2; rr++) {
        const int idx = rr * 512 + tid;
        const int bl = idx >> 7, h = idx & 127;
        float s = 0.f;
        #pragma unroll
        for (int d = 0; d < 16; d++) s += h1s[(bl * 16 + d) * 132 + h];
        out[(b0 + bl) * HOUT + h] = s;
    }
    CP_WAIT0();
    __syncthreads();

    // ================= Layer 2 =================
    #pragma unroll
    for (int mt = 0; mt < 2; mt++)
        #pragma unroll
        for (int ht = 0; ht < 4; ht++)
            #pragma unroll
            for (int j = 0; j < 4; j++) acc[mt][ht][j] = 0.f;

    {
        float hv[2][2][8];
        #pragma unroll 1
        for (int cc = 0; cc < NC2; cc += 2) {
            {
                const int qq = cc / 39, f = cc - qq * 39;
                if (f == 0) load_res_l2(h1s, hv, qq, m0, r, c2);
                mma_l2(sb, xs, cc & 3, f, hv, acc, m0, r, bRow2, bHalf, bXor, bSel);
            }
            {
                const int ci = cc + 1;
                const int qq = ci / 39, f = ci - qq * 39;
                if (f == 0) load_res_l2(h1s, hv, qq, m0, r, c2);
                mma_l2(sb, xs, ci & 3, f, hv, acc, m0, r, bRow2, bHalf, bXor, bSel);
            }
            CP_WAIT0();
            __syncthreads();
            if (cc + 4 < NC2) {
                stage_l2(sb, (cc + 4) & 3, cc + 4, tid);
                stage_l2(sb, (cc + 5) & 3, cc + 5, tid);
                CP_COMMIT();
            }
        }
    }

    // L2 epilogue
    #pragma unroll
    for (int mt = 0; mt < 2; mt++)
        #pragma unroll
        for (int ht = 0; ht < 4; ht++) {
            const int n = m0 + mt * 16 + r;
            const int h = h0 + ht * 8 + c2;
            *(float2*)&h1s[n * 132 + h] = make_float2(acc[mt][ht][0], acc[mt][ht][1]);
            *(float2*)&h1s[(n + 8) * 132 + h] = make_float2(acc[mt][ht][2], acc[mt][ht][3]);
        }
    __syncthreads();
    #pragma unroll
    for (int rr = 0; rr < 2; rr++) {
        const int idx = rr * 512 + tid;
        const int bl = idx >> 7, h = idx & 127;
        float s = 0.f;
        #pragma unroll
        for (int d = 0; d < 16; d++) s += h1s[(bl * 16 + d) * 132 + h];
        out[(b0 + bl) * HOUT + 128 + h] = s;
    }
}

extern "C" void kernel_launch(void* const* d_in, const int* in_sizes, int n_in,
                              void* d_out, int out_size) {
    const float* xin = (const float*)d_in[0];
    const float* W0  = (const float*)d_in[1];
    const float* W1  = (const float*)d_in[2];
    float* out = (float*)d_out;

    prep_w1<<<(NF1 * 8192 + 255) / 256, 256>>>(W0);
    prep_w2<<<(NC2 * 4096 + 255) / 256, 256>>>(W1);

    cudaFuncSetAttribute(cin_main, cudaFuncAttributeMaxDynamicSharedMemorySize, SMEM_TOTAL);
    cin_main<<<256, 512, SMEM_TOTAL>>>(xin, out);
}